// round 2
// baseline (speedup 1.0000x reference)
#include <cuda_runtime.h>
#include <cstdint>

// Gather: out[i] = X[indices[i].row * W + indices[i].col]
// X: 4096 x 4096 fp32 (64 MB), indices: N_IDX x 2 int32, out: N_IDX fp32.
//
// R2 strategy: latency-hiding via occupancy. 2 outputs per thread
// (one int4 index load -> 2 independent gathers -> one float2 store),
// 262144 threads = 8192 warps = ~55 warps/SM (single full wave on 148 SMs).
// All loads L2-only (__ldcg): L1 is flushed per launch and random gathers
// have zero L1 reuse, so skip L1 allocation entirely.

#define W_DIM 4096

__global__ void __launch_bounds__(256) cubical_gather_kernel(
    const float* __restrict__ X,
    const int4* __restrict__ idx4,    // indices as int4: {r0,c0,r1,c1}
    float2* __restrict__ out2,
    int n_vec)                         // number of float2 outputs
{
    int t = blockIdx.x * blockDim.x + threadIdx.x;
    if (t >= n_vec) return;

    // One int4 load = 2 (row,col) pairs for outputs [2t, 2t+1]
    int4 p = __ldcg(&idx4[t]);

    // Independent addresses -> both gathers issue back-to-back (MLP=2/thread,
    // 55 warps/SM of these chains interleave to hide L2/DRAM latency).
    int o0 = (p.x << 12) + p.y;   // r * 4096 + c
    int o1 = (p.z << 12) + p.w;

    float2 v;
    v.x = __ldcg(X + o0);
    v.y = __ldcg(X + o1);

    out2[t] = v;
}

extern "C" void kernel_launch(void* const* d_in, const int* in_sizes, int n_in,
                              void* d_out, int out_size)
{
    const float* X   = (const float*)d_in[0];   // 4096*4096 fp32
    const int*   idx = (const int*)d_in[1];     // N_IDX*2 int32

    int n_out = out_size;        // 524288 fp32 elements
    int n_vec = n_out / 2;       // 262144 float2 outputs

    int threads = 256;
    int blocks  = (n_vec + threads - 1) / threads;   // 1024

    cubical_gather_kernel<<<blocks, threads>>>(
        X, (const int4*)idx, (float2*)d_out, n_vec);
}